// round 10
// baseline (speedup 1.0000x reference)
#include <cuda_runtime.h>
#include <math.h>

#define NN 768          // n_nuclei
#define CNT 767.0f      // edges per sender
#define NT 24           // 32-wide node tiles
#define EDGE_GRID 600   // 2 half-blocks per tile, single wave on 152 SMs @ occ 4

typedef unsigned long long ull;

// ---------------- scratch (static device globals; no allocation) ----------------
__device__ __align__(16) float g_embed0[NN*32];
__device__ __align__(16) float g_acc1[NN*32];
__device__ __align__(16) float g_e1[NN*64];
__device__ __align__(16) float g_acc2[NN*32];
__device__ float g_aggsum[160];
__device__ unsigned g_done;
// sender/receiver projections, transposed+packed: T[(f>>1)*1536 + n*2 + (f&1)]
__device__ __align__(16) float g_B1t[16*NN*2];
__device__ __align__(16) float g_P1t[16*NN*2];
__device__ __align__(16) float g_B2t[16*NN*2];
__device__ __align__(16) float g_P2t[16*NN*2];

// RBF projection weights (rows 64..95 of mp1_w0, rows 128..159 of mp2_w0), row-major 32x32
__constant__ __align__(16) float cWe[2][32*32];

__device__ __forceinline__ float silu_f(float x) {          // exact-ish (node kernels)
    return __fdividef(x, 1.0f + __expf(-x));
}
__device__ __forceinline__ float silu_t(float x) {          // 1-MUFU (edge kernels)
    float xh = 0.5f * x, t;
    asm("tanh.approx.f32 %0, %1;" : "=f"(t) : "f"(xh));
    return fmaf(xh, t, xh);                                  // x/2*(1+tanh(x/2))
}
__device__ __forceinline__ float wsum(float v) {             // warp allreduce
    v += __shfl_xor_sync(0xffffffffu, v, 16);
    v += __shfl_xor_sync(0xffffffffu, v, 8);
    v += __shfl_xor_sync(0xffffffffu, v, 4);
    v += __shfl_xor_sync(0xffffffffu, v, 2);
    v += __shfl_xor_sync(0xffffffffu, v, 1);
    return v;
}

// ---- packed fp32x2 helpers (Blackwell) ----
__device__ __forceinline__ ull pk2(float lo, float hi) {
    ull r; asm("mov.b64 %0, {%1,%2};" : "=l"(r) : "f"(lo), "f"(hi)); return r;
}
__device__ __forceinline__ void upk2(ull v, float& lo, float& hi) {
    asm("mov.b64 {%0,%1}, %2;" : "=f"(lo), "=f"(hi) : "l"(v));
}
__device__ __forceinline__ ull fma2(ull a, ull b, ull c) {
    ull d; asm("fma.rn.f32x2 %0, %1, %2, %3;" : "=l"(d) : "l"(a), "l"(b), "l"(c)); return d;
}
__device__ __forceinline__ ull add2(ull a, ull b) {
    ull d; asm("add.rn.f32x2 %0, %1, %2;" : "=l"(d) : "l"(a), "l"(b)); return d;
}

// ---------------- pass 0: node embeddings + layer-1 projections + scratch reset ----
__global__ void prep_kernel(const float* __restrict__ embed_table,
                            const int*   __restrict__ charges,
                            const float* __restrict__ mp1_w0,
                            const float* __restrict__ mp1_b0)
{
    int gid = blockIdx.x * blockDim.x + threadIdx.x;   // 0 .. 768*32-1
    int n = gid >> 5, j = gid & 31;
    int c = charges[n];
    const float* er = embed_table + c * 32;
    float e0 = er[j];
    g_embed0[n*32 + j] = e0;
    float a = mp1_b0[j], b = 0.0f;
    #pragma unroll
    for (int k = 0; k < 32; k++) {
        float e = er[k];
        a = fmaf(e, mp1_w0[k*32 + j],        a);
        b = fmaf(e, mp1_w0[(32 + k)*32 + j], b);
    }
    g_B1t[(j >> 1)*(2*NN) + n*2 + (j & 1)] = a;
    g_P1t[(j >> 1)*(2*NN) + n*2 + (j & 1)] = b;
    g_acc1[gid] = 0.0f;
    g_acc2[gid] = 0.0f;
    if (gid < 160) g_aggsum[gid] = 0.0f;
    if (gid == 0)  g_done = 0u;
}

// ---------------- edge pass (layer L): symmetric pair tiles, fused dual-row k-loop ----
// block = (tile, half): 16 i-rows x 32 j-cols; warp: lane=j, 2 fused i-rows.
template <int L>
__global__ __launch_bounds__(256, 4) void edge_kernel(const float* __restrict__ nuclei)
{
    __shared__ ull smStage[8][32][9];   // padded to break bank conflicts
    const ull* bt = reinterpret_cast<const ull*>((L == 0) ? g_B1t : g_B2t);
    const ull* pt = reinterpret_cast<const ull*>((L == 0) ? g_P1t : g_P2t);
    float*   accO = (L == 0) ? g_acc1 : g_acc2;
    const ulonglong2* w4 = reinterpret_cast<const ulonglong2*>(&cWe[L][0]);

    int tile = blockIdx.x >> 1, sub = blockIdx.x & 1;
    int tI = 0, rem = tile;
    while (rem >= NT - tI) { rem -= NT - tI; tI++; }
    const int tJ = tI + rem;
    const bool diag = (tI == tJ);

    const int wid = threadIdx.x >> 5, lane = threadIdx.x & 31;
    const int j = tJ*32 + lane;
    const float jx = __ldg(&nuclei[j*3 + 0]);
    const float jy = __ldg(&nuclei[j*3 + 1]);
    const float jz = __ldg(&nuclei[j*3 + 2]);
    const int i0 = tI*32 + sub*16 + wid*2;
    const int i1 = i0 + 1;

    // geometry for both i-rows
    float si0, tc0, pf0, mf0, si1, tc1, pf1, mf1;
    {
        float dx = jx - __ldg(&nuclei[i0*3 + 0]);
        float dy = jy - __ldg(&nuclei[i0*3 + 1]);
        float dz = jz - __ldg(&nuclei[i0*3 + 2]);
        float d2 = fmaf(dx, dx, fmaf(dy, dy, dz*dz));
        mf0 = (i0 == j) ? 0.0f : 1.0f;
        d2 = (i0 == j) ? 1.0f : d2;
        float rsq = rsqrtf(d2);
        float co;
        __sincosf(d2 * rsq * 0.31415926535897931f, &si0, &co);
        tc0 = co + co;
        pf0 = 0.44721359549995794f * rsq;
    }
    {
        float dx = jx - __ldg(&nuclei[i1*3 + 0]);
        float dy = jy - __ldg(&nuclei[i1*3 + 1]);
        float dz = jz - __ldg(&nuclei[i1*3 + 2]);
        float d2 = fmaf(dx, dx, fmaf(dy, dy, dz*dz));
        mf1 = (i1 == j) ? 0.0f : 1.0f;
        d2 = (i1 == j) ? 1.0f : d2;
        float rsq = rsqrtf(d2);
        float co;
        __sincosf(d2 * rsq * 0.31415926535897931f, &si1, &co);
        tc1 = co + co;
        pf1 = 0.44721359549995794f * rsq;
    }

    #pragma unroll
    for (int P = 0; P < 2; P++) {
        // fused dual-row Chebyshev matvec: one weight load serves both i-rows
        ull acc0[8], acc1[8];
        #pragma unroll
        for (int u = 0; u < 8; u++) { acc0[u] = 0ULL; acc1[u] = 0ULL; }
        float sp0 = 0.0f, sc0 = si0;
        float sp1 = 0.0f, sc1 = si1;
        #pragma unroll
        for (int k = 0; k < 32; k++) {
            ulonglong2 wa = w4[k*8 + P*4 + 0];
            ulonglong2 wb = w4[k*8 + P*4 + 1];
            ulonglong2 wc = w4[k*8 + P*4 + 2];
            ulonglong2 wd = w4[k*8 + P*4 + 3];
            ull s20 = pk2(sc0, sc0), s21 = pk2(sc1, sc1);
            acc0[0] = fma2(s20, wa.x, acc0[0]); acc1[0] = fma2(s21, wa.x, acc1[0]);
            acc0[1] = fma2(s20, wa.y, acc0[1]); acc1[1] = fma2(s21, wa.y, acc1[1]);
            acc0[2] = fma2(s20, wb.x, acc0[2]); acc1[2] = fma2(s21, wb.x, acc1[2]);
            acc0[3] = fma2(s20, wb.y, acc0[3]); acc1[3] = fma2(s21, wb.y, acc1[3]);
            acc0[4] = fma2(s20, wc.x, acc0[4]); acc1[4] = fma2(s21, wc.x, acc1[4]);
            acc0[5] = fma2(s20, wc.y, acc0[5]); acc1[5] = fma2(s21, wc.y, acc1[5]);
            acc0[6] = fma2(s20, wd.x, acc0[6]); acc1[6] = fma2(s21, wd.x, acc1[6]);
            acc0[7] = fma2(s20, wd.y, acc0[7]); acc1[7] = fma2(s21, wd.y, acc1[7]);
            float sn0 = fmaf(tc0, sc0, -sp0); sp0 = sc0; sc0 = sn0;
            float sn1 = fmaf(tc1, sc1, -sp1); sp1 = sc1; sc1 = sn1;
        }

        const ull pref0 = pk2(pf0, pf0), pref1 = pk2(pf1, pf1);
        const ull m20 = pk2(mf0, mf0),  m21 = pk2(mf1, mf1);

        // streaming epilogue per u: fwd allreduce + atomic, bwd -> smem stage
        #pragma unroll
        for (int u = 0; u < 8; u++) {
            const int f = (P*8 + u)*NN;
            // forward: sender i, receiver j
            ull pj  = __ldg(&pt[f + j]);                  // coalesced, shared by both rows
            ull bi0 = __ldg(&bt[f + i0]);                 // uniform
            ull bi1 = __ldg(&bt[f + i1]);
            ull h0 = fma2(pref0, acc0[u], add2(bi0, pj));
            ull h1 = fma2(pref1, acc1[u], add2(bi1, pj));
            float h0l, h0h, h1l, h1h;
            upk2(h0, h0l, h0h); upk2(h1, h1l, h1h);
            float f00 = wsum(silu_t(h0l) * mf0);
            float f01 = wsum(silu_t(h0h) * mf0);
            float f10 = wsum(silu_t(h1l) * mf1);
            float f11 = wsum(silu_t(h1h) * mf1);
            if (lane == 0) {
                atomicAdd(&accO[i0*32 + P*16 + 2*u],     f00);
                atomicAdd(&accO[i0*32 + P*16 + 2*u + 1], f01);
                atomicAdd(&accO[i1*32 + P*16 + 2*u],     f10);
                atomicAdd(&accO[i1*32 + P*16 + 2*u + 1], f11);
            }
            // backward: sender j, receiver i (skip on diagonal tiles)
            if (!diag) {
                ull bj  = __ldg(&bt[f + j]);              // coalesced, shared
                ull pi0 = __ldg(&pt[f + i0]);             // uniform
                ull pi1 = __ldg(&pt[f + i1]);
                ull g0 = fma2(pref0, acc0[u], add2(bj, pi0));
                ull g1 = fma2(pref1, acc1[u], add2(bj, pi1));
                float g0l, g0h, g1l, g1h;
                upk2(g0, g0l, g0h); upk2(g1, g1l, g1h);
                ull bw = fma2(pk2(silu_t(g0l), silu_t(g0h)), m20,
                              fma2(pk2(silu_t(g1l), silu_t(g1h)), m21, 0ULL));
                smStage[wid][lane][u] = bw;
            }
        }

        if (!diag) {   // uniform branch per block: barriers are safe
            __syncthreads();
            {
                int jl = threadIdx.x >> 3, u = threadIdx.x & 7;
                ull a = smStage[0][jl][u];
                #pragma unroll
                for (int w = 1; w < 8; w++) a = add2(a, smStage[w][jl][u]);
                float lo, hi; upk2(a, lo, hi);
                atomicAdd(&accO[(tJ*32 + jl)*32 + P*16 + 2*u],     lo);
                atomicAdd(&accO[(tJ*32 + jl)*32 + P*16 + 2*u + 1], hi);
            }
            __syncthreads();   // stage buffer reused by next pass
        }
    }
}

// ---------------- pass 2: layer-1 node update + layer-2 projections ----------------
__global__ __launch_bounds__(64) void node1_kernel(
    const float* __restrict__ mp1_w1, const float* __restrict__ mp1_b1,
    const float* __restrict__ up1_w0, const float* __restrict__ up1_b0,
    const float* __restrict__ up1_w1, const float* __restrict__ up1_b1,
    const float* __restrict__ mp2_w0, const float* __restrict__ mp2_b0)
{
    int n = blockIdx.x, t = threadIdx.x;
    __shared__ float in64[64], h[64], e1[64], m[32];
    if (t < 32) {
        in64[t] = g_embed0[n*32 + t];
        m[t] = g_acc1[n*32 + t] * (1.0f / CNT);
    }
    __syncthreads();
    if (t < 32) {
        float a = mp1_b1[t];
        #pragma unroll
        for (int k = 0; k < 32; k++) a = fmaf(m[k], mp1_w1[k*32 + t], a);
        in64[32 + t] = a;
    }
    __syncthreads();
    {
        float a = up1_b0[t];
        #pragma unroll 8
        for (int k = 0; k < 64; k++) a = fmaf(in64[k], up1_w0[k*64 + t], a);
        h[t] = silu_f(a);
    }
    __syncthreads();
    {
        float a = up1_b1[t];
        #pragma unroll 8
        for (int k = 0; k < 64; k++) a = fmaf(h[k], up1_w1[k*64 + t], a);
        e1[t] = a;
        g_e1[n*64 + t] = a;
    }
    __syncthreads();
    if (t < 32) {
        float a = mp2_b0[t], b = 0.0f;
        #pragma unroll 8
        for (int k = 0; k < 64; k++) {
            float e = e1[k];
            a = fmaf(e, mp2_w0[k*32 + t],        a);
            b = fmaf(e, mp2_w0[(64 + k)*32 + t], b);
        }
        g_B2t[(t >> 1)*(2*NN) + n*2 + (t & 1)] = a;
        g_P2t[(t >> 1)*(2*NN) + n*2 + (t & 1)] = b;
    }
}

// ---------------- pass 4: layer-2 node update + node readout + agg sum + global ----
__global__ __launch_bounds__(64) void node2_kernel(
    const int*   __restrict__ charges,
    const float* __restrict__ mp2_w1, const float* __restrict__ mp2_b1,
    const float* __restrict__ up2_w0, const float* __restrict__ up2_b0,
    const float* __restrict__ up2_w1, const float* __restrict__ up2_b1,
    const float* __restrict__ no_w0,  const float* __restrict__ no_b0,
    const float* __restrict__ no_w1,  const float* __restrict__ no_embed,
    const float* __restrict__ go_w0,  const float* __restrict__ go_b0,
    const float* __restrict__ go_w1,  const float* __restrict__ go_b1,
    float* __restrict__ out)
{
    int n = blockIdx.x, t = threadIdx.x;
    __shared__ float agg[160], in96[96], h[64], m[32], t3[3];
    __shared__ unsigned lastFlag;
    if (t < 32) {
        m[t] = g_acc2[n*32 + t] * (1.0f / CNT);
        agg[t] = g_embed0[n*32 + t];
    }
    float e1v = g_e1[n*64 + t];
    agg[32 + t] = e1v;
    in96[t] = e1v;
    __syncthreads();
    if (t < 32) {
        float a = mp2_b1[t];
        #pragma unroll
        for (int k = 0; k < 32; k++) a = fmaf(m[k], mp2_w1[k*32 + t], a);
        in96[64 + t] = a;
    }
    __syncthreads();
    {
        float a = up2_b0[t];
        #pragma unroll 8
        for (int k = 0; k < 96; k++) a = fmaf(in96[k], up2_w0[k*64 + t], a);
        h[t] = silu_f(a);
    }
    __syncthreads();
    {
        float a = up2_b1[t] + e1v;
        #pragma unroll 8
        for (int k = 0; k < 64; k++) a = fmaf(h[k], up2_w1[k*64 + t], a);
        agg[96 + t] = a;   // n_embed2 (residual)
    }
    __syncthreads();
    if (t < 3) {
        float a = no_b0[t];
        for (int k = 0; k < 160; k++) a = fmaf(agg[k], no_w0[k*3 + t], a);
        t3[t] = silu_f(a);
    }
    for (int i = t; i < 160; i += 64) atomicAdd(&g_aggsum[i], agg[i]);
    __syncthreads();
    if (t < 3) {
        int c = charges[n];
        float o = no_embed[c*3 + t];
        #pragma unroll
        for (int k = 0; k < 3; k++) o = fmaf(t3[k], no_w1[k*3 + t], o);
        out[n*3 + t] = o;
    }

    // ---- last block computes the global readout ----
    __threadfence();
    if (t == 0) lastFlag = (atomicAdd(&g_done, 1u) == (unsigned)(NN - 1)) ? 1u : 0u;
    __syncthreads();
    if (lastFlag) {
        __shared__ float red[64];
        float p = 0.0f;
        for (int i = t; i < 160; i += 64) p += g_aggsum[i] * go_w0[i];
        red[t] = p;
        __syncthreads();
        for (int sft = 32; sft > 0; sft >>= 1) {
            if (t < sft) red[t] += red[t + sft];
            __syncthreads();
        }
        if (t == 0) {
            float hh = silu_f(red[0] * (1.0f / (float)NN) + go_b0[0]);
            out[NN*3] = fmaf(hh, go_w1[0], go_b1[0]);
        }
    }
}

// ---------------- host-side launch ----------------
extern "C" void kernel_launch(void* const* d_in, const int* in_sizes, int n_in,
                              void* d_out, int out_size)
{
    const float* nuclei      = (const float*)d_in[0];
    const int*   charges     = (const int*)  d_in[1];
    // d_in[2] = f (values known analytically: (k+1)*pi)
    const float* embed_table = (const float*)d_in[3];
    const float* mp1_w0 = (const float*)d_in[4];
    const float* mp1_b0 = (const float*)d_in[5];
    const float* mp1_w1 = (const float*)d_in[6];
    const float* mp1_b1 = (const float*)d_in[7];
    const float* up1_w0 = (const float*)d_in[8];
    const float* up1_b0 = (const float*)d_in[9];
    const float* up1_w1 = (const float*)d_in[10];
    const float* up1_b1 = (const float*)d_in[11];
    const float* mp2_w0 = (const float*)d_in[12];
    const float* mp2_b0 = (const float*)d_in[13];
    const float* mp2_w1 = (const float*)d_in[14];
    const float* mp2_b1 = (const float*)d_in[15];
    const float* up2_w0 = (const float*)d_in[16];
    const float* up2_b0 = (const float*)d_in[17];
    const float* up2_w1 = (const float*)d_in[18];
    const float* up2_b1 = (const float*)d_in[19];
    const float* no_w0  = (const float*)d_in[20];
    const float* no_b0  = (const float*)d_in[21];
    const float* no_w1  = (const float*)d_in[22];
    const float* no_emb = (const float*)d_in[23];
    const float* go_w0  = (const float*)d_in[24];
    const float* go_b0  = (const float*)d_in[25];
    const float* go_w1  = (const float*)d_in[26];
    const float* go_b1  = (const float*)d_in[27];
    float* out = (float*)d_out;

    // RBF projection weights -> constant memory (contiguous row blocks)
    void* cwAddr = nullptr;
    cudaGetSymbolAddress(&cwAddr, cWe);
    cudaMemcpyAsync((char*)cwAddr,        mp1_w0 + 64*32,  4096, cudaMemcpyDeviceToDevice);
    cudaMemcpyAsync((char*)cwAddr + 4096, mp2_w0 + 128*32, 4096, cudaMemcpyDeviceToDevice);

    prep_kernel<<<NN*32/256, 256>>>(embed_table, charges, mp1_w0, mp1_b0);
    edge_kernel<0><<<EDGE_GRID, 256>>>(nuclei);
    node1_kernel<<<NN, 64>>>(mp1_w1, mp1_b1, up1_w0, up1_b0, up1_w1, up1_b1, mp2_w0, mp2_b0);
    edge_kernel<1><<<EDGE_GRID, 256>>>(nuclei);
    node2_kernel<<<NN, 64>>>(charges, mp2_w1, mp2_b1, up2_w0, up2_b0, up2_w1, up2_b1,
                             no_w0, no_b0, no_w1, no_emb,
                             go_w0, go_b0, go_w1, go_b1, out);
}

// round 11
// speedup vs baseline: 1.2178x; 1.2178x over previous
#include <cuda_runtime.h>
#include <math.h>

#define NN 768
#define CNT 767.0f
#define NT 24
#define EDGE_GRID 600

typedef unsigned long long ull;

__device__ __align__(16) float g_embed0[NN*32];
__device__ __align__(16) float g_acc1[NN*32];
__device__ __align__(16) float g_e1[NN*64];
__device__ __align__(16) float g_acc2[NN*32];
__device__ float g_aggsum[160];
__device__ unsigned g_done;
__device__ __align__(16) float g_B1t[16*NN*2];
__device__ __align__(16) float g_P1t[16*NN*2];
__device__ __align__(16) float g_B2t[16*NN*2];
__device__ __align__(16) float g_P2t[16*NN*2];

__constant__ __align__(16) float cWe[2][32*32];

__device__ __forceinline__ float silu_f(float x) {
    return __fdividef(x, 1.0f + __expf(-x));
}
__device__ __forceinline__ float silu_t(float x) {
    float xh = 0.5f * x, t;
    asm("tanh.approx.f32 %0, %1;" : "=f"(t) : "f"(xh));
    return fmaf(xh, t, xh);
}

__device__ __forceinline__ ull pk2(float lo, float hi) {
    ull r; asm("mov.b64 %0, {%1,%2};" : "=l"(r) : "f"(lo), "f"(hi)); return r;
}
__device__ __forceinline__ void upk2(ull v, float& lo, float& hi) {
    asm("mov.b64 {%0,%1}, %2;" : "=f"(lo), "=f"(hi) : "l"(v));
}
__device__ __forceinline__ ull fma2(ull a, ull b, ull c) {
    ull d; asm("fma.rn.f32x2 %0, %1, %2, %3;" : "=l"(d) : "l"(a), "l"(b), "l"(c)); return d;
}
__device__ __forceinline__ ull add2(ull a, ull b) {
    ull d; asm("add.rn.f32x2 %0, %1, %2;" : "=l"(d) : "l"(a), "l"(b)); return d;
}

__global__ void prep_kernel(const float* __restrict__ embed_table,
                            const int*   __restrict__ charges,
                            const float* __restrict__ mp1_w0,
                            const float* __restrict__ mp1_b0)
{
    int gid = blockIdx.x * blockDim.x + threadIdx.x;
    int n = gid >> 5, j = gid & 31;
    int c = charges[n];
    const float* er = embed_table + c * 32;
    float e0 = er[j];
    g_embed0[n*32 + j] = e0;
    float a = mp1_b0[j], b = 0.0f;
    #pragma unroll
    for (int k = 0; k < 32; k++) {
        float e = er[k];
        a = fmaf(e, mp1_w0[k*32 + j],        a);
        b = fmaf(e, mp1_w0[(32 + k)*32 + j], b);
    }
    g_B1t[(j >> 1)*(2*NN) + n*2 + (j & 1)] = a;
    g_P1t[(j >> 1)*(2*NN) + n*2 + (j & 1)] = b;
    g_acc1[gid] = 0.0f;
    g_acc2[gid] = 0.0f;
    if (gid < 160) g_aggsum[gid] = 0.0f;
    if (gid == 0)  g_done = 0u;
}

// edge pass: symmetric pair tiles; 16 i-rows x 32 j-cols per block, 2 i-rows per warp
template <int L>
__global__ __launch_bounds__(256, 4) void edge_kernel(const float* __restrict__ nuclei)
{
    __shared__ ull smStage[8][32][9];
    const ull* bt = reinterpret_cast<const ull*>((L == 0) ? g_B1t : g_B2t);
    const ull* pt = reinterpret_cast<const ull*>((L == 0) ? g_P1t : g_P2t);
    float*   accO = (L == 0) ? g_acc1 : g_acc2;
    const ulonglong2* w4 = reinterpret_cast<const ulonglong2*>(&cWe[L][0]);

    int tile = blockIdx.x >> 1, sub = blockIdx.x & 1;
    int tI = 0, rem = tile;
    while (rem >= NT - tI) { rem -= NT - tI; tI++; }
    const int tJ = tI + rem;
    const bool diag = (tI == tJ);

    const int wid = threadIdx.x >> 5, lane = threadIdx.x & 31;
    const int j = tJ*32 + lane;
    const float jx = __ldg(&nuclei[j*3 + 0]);
    const float jy = __ldg(&nuclei[j*3 + 1]);
    const float jz = __ldg(&nuclei[j*3 + 2]);
    // transpose-reduce feature index for this lane (bits 4..1)
    const int fidx = ((lane >> 4) & 1)*8 + ((lane >> 3) & 1)*4
                   + ((lane >> 2) & 1)*2 + ((lane >> 1) & 1);

    #pragma unroll
    for (int P = 0; P < 2; P++) {
        ull colsum[8];
        #pragma unroll
        for (int u = 0; u < 8; u++) colsum[u] = 0ULL;

        #pragma unroll
        for (int ii = 0; ii < 2; ii++) {
            const int i = tI*32 + sub*16 + wid*2 + ii;
            float dx = jx - __ldg(&nuclei[i*3 + 0]);
            float dy = jy - __ldg(&nuclei[i*3 + 1]);
            float dz = jz - __ldg(&nuclei[i*3 + 2]);
            float d2 = fmaf(dx, dx, fmaf(dy, dy, dz*dz));
            float mf = (i == j) ? 0.0f : 1.0f;
            d2 = (i == j) ? 1.0f : d2;
            float rsq = rsqrtf(d2);
            float si, co;
            __sincosf(d2 * rsq * 0.31415926535897931f, &si, &co);
            float twoc = co + co;

            ull acc[8];
            #pragma unroll
            for (int u = 0; u < 8; u++) acc[u] = 0ULL;
            float sp = 0.0f, sc = si;
            #pragma unroll
            for (int k = 0; k < 32; k++) {
                ulonglong2 wa = w4[k*8 + P*4 + 0];
                ulonglong2 wb = w4[k*8 + P*4 + 1];
                ulonglong2 wc = w4[k*8 + P*4 + 2];
                ulonglong2 wd = w4[k*8 + P*4 + 3];
                ull s2 = pk2(sc, sc);
                acc[0] = fma2(s2, wa.x, acc[0]); acc[1] = fma2(s2, wa.y, acc[1]);
                acc[2] = fma2(s2, wb.x, acc[2]); acc[3] = fma2(s2, wb.y, acc[3]);
                acc[4] = fma2(s2, wc.x, acc[4]); acc[5] = fma2(s2, wc.y, acc[5]);
                acc[6] = fma2(s2, wd.x, acc[6]); acc[7] = fma2(s2, wd.y, acc[7]);
                float sn = fmaf(twoc, sc, -sp); sp = sc; sc = sn;
            }
            float pf = 0.44721359549995794f * rsq;
            ull pref2 = pk2(pf, pf);

            // forward: sender i, receiver j -> acc[i]
            float fs[16];
            #pragma unroll
            for (int u = 0; u < 8; u++) {
                ull bi = __ldg(&bt[(P*8 + u)*NN + i]);   // uniform
                ull pj = __ldg(&pt[(P*8 + u)*NN + j]);   // coalesced
                ull h2 = fma2(pref2, acc[u], add2(bi, pj));
                float hl, hg; upk2(h2, hl, hg);
                fs[2*u]   = silu_t(hl) * mf;
                fs[2*u+1] = silu_t(hg) * mf;
            }
            // transpose-reduce: 16 shfls; even lanes end with one feature sum each
            float v8[8];
            #pragma unroll
            for (int f = 0; f < 8; f++) {
                float keep = (lane & 16) ? fs[f+8] : fs[f];
                float send = (lane & 16) ? fs[f]   : fs[f+8];
                v8[f] = keep + __shfl_xor_sync(0xffffffffu, send, 16);
            }
            float v4[4];
            #pragma unroll
            for (int f = 0; f < 4; f++) {
                float keep = (lane & 8) ? v8[f+4] : v8[f];
                float send = (lane & 8) ? v8[f]   : v8[f+4];
                v4[f] = keep + __shfl_xor_sync(0xffffffffu, send, 8);
            }
            float v2[2];
            #pragma unroll
            for (int f = 0; f < 2; f++) {
                float keep = (lane & 4) ? v2[0] : v2[0];  // placeholder (replaced below)
                (void)keep;
                float k2 = (lane & 4) ? v4[f+2] : v4[f];
                float s2 = (lane & 4) ? v4[f]   : v4[f+2];
                v2[f] = k2 + __shfl_xor_sync(0xffffffffu, s2, 4);
            }
            float k1 = (lane & 2) ? v2[1] : v2[0];
            float s1 = (lane & 2) ? v2[0] : v2[1];
            float v1 = k1 + __shfl_xor_sync(0xffffffffu, s1, 2);
            float v0 = v1 + __shfl_xor_sync(0xffffffffu, v1, 1);
            if (!(lane & 1))
                atomicAdd(&accO[i*32 + P*16 + fidx], v0);

            // backward: sender j, receiver i (skip on diagonal tiles)
            if (!diag) {
                ull m2 = pk2(mf, mf);
                #pragma unroll
                for (int u = 0; u < 8; u++) {
                    ull bj = __ldg(&bt[(P*8 + u)*NN + j]);   // coalesced
                    ull pi = __ldg(&pt[(P*8 + u)*NN + i]);   // uniform
                    ull g2 = fma2(pref2, acc[u], add2(bj, pi));
                    float gl, gg; upk2(g2, gl, gg);
                    colsum[u] = fma2(pk2(silu_t(gl), silu_t(gg)), m2, colsum[u]);
                }
            }
        }

        if (!diag) {
            #pragma unroll
            for (int u = 0; u < 8; u++) smStage[wid][lane][u] = colsum[u];
            __syncthreads();
            {
                int jl = threadIdx.x >> 3, u = threadIdx.x & 7;
                ull a = smStage[0][jl][u];
                #pragma unroll
                for (int w = 1; w < 8; w++) a = add2(a, smStage[w][jl][u]);
                float lo, hi; upk2(a, lo, hi);
                atomicAdd(&accO[(tJ*32 + jl)*32 + P*16 + 2*u],     lo);
                atomicAdd(&accO[(tJ*32 + jl)*32 + P*16 + 2*u + 1], hi);
            }
            __syncthreads();
        }
    }
}

__global__ __launch_bounds__(64) void node1_kernel(
    const float* __restrict__ mp1_w1, const float* __restrict__ mp1_b1,
    const float* __restrict__ up1_w0, const float* __restrict__ up1_b0,
    const float* __restrict__ up1_w1, const float* __restrict__ up1_b1,
    const float* __restrict__ mp2_w0, const float* __restrict__ mp2_b0)
{
    int n = blockIdx.x, t = threadIdx.x;
    __shared__ float in64[64], h[64], e1[64], m[32];
    if (t < 32) {
        in64[t] = g_embed0[n*32 + t];
        m[t] = g_acc1[n*32 + t] * (1.0f / CNT);
    }
    __syncthreads();
    if (t < 32) {
        float a = mp1_b1[t];
        #pragma unroll
        for (int k = 0; k < 32; k++) a = fmaf(m[k], mp1_w1[k*32 + t], a);
        in64[32 + t] = a;
    }
    __syncthreads();
    {
        float a = up1_b0[t];
        #pragma unroll 8
        for (int k = 0; k < 64; k++) a = fmaf(in64[k], up1_w0[k*64 + t], a);
        h[t] = silu_f(a);
    }
    __syncthreads();
    {
        float a = up1_b1[t];
        #pragma unroll 8
        for (int k = 0; k < 64; k++) a = fmaf(h[k], up1_w1[k*64 + t], a);
        e1[t] = a;
        g_e1[n*64 + t] = a;
    }
    __syncthreads();
    if (t < 32) {
        float a = mp2_b0[t], b = 0.0f;
        #pragma unroll 8
        for (int k = 0; k < 64; k++) {
            float e = e1[k];
            a = fmaf(e, mp2_w0[k*32 + t],        a);
            b = fmaf(e, mp2_w0[(64 + k)*32 + t], b);
        }
        g_B2t[(t >> 1)*(2*NN) + n*2 + (t & 1)] = a;
        g_P2t[(t >> 1)*(2*NN) + n*2 + (t & 1)] = b;
    }
}

__global__ __launch_bounds__(64) void node2_kernel(
    const int*   __restrict__ charges,
    const float* __restrict__ mp2_w1, const float* __restrict__ mp2_b1,
    const float* __restrict__ up2_w0, const float* __restrict__ up2_b0,
    const float* __restrict__ up2_w1, const float* __restrict__ up2_b1,
    const float* __restrict__ no_w0,  const float* __restrict__ no_b0,
    const float* __restrict__ no_w1,  const float* __restrict__ no_embed,
    const float* __restrict__ go_w0,  const float* __restrict__ go_b0,
    const float* __restrict__ go_w1,  const float* __restrict__ go_b1,
    float* __restrict__ out)
{
    int n = blockIdx.x, t = threadIdx.x;
    __shared__ float agg[160], in96[96], h[64], m[32], t3[3];
    __shared__ unsigned lastFlag;
    if (t < 32) {
        m[t] = g_acc2[n*32 + t] * (1.0f / CNT);
        agg[t] = g_embed0[n*32 + t];
    }
    float e1v = g_e1[n*64 + t];
    agg[32 + t] = e1v;
    in96[t] = e1v;
    __syncthreads();
    if (t < 32) {
        float a = mp2_b1[t];
        #pragma unroll
        for (int k = 0; k < 32; k++) a = fmaf(m[k], mp2_w1[k*32 + t], a);
        in96[64 + t] = a;
    }
    __syncthreads();
    {
        float a = up2_b0[t];
        #pragma unroll 8
        for (int k = 0; k < 96; k++) a = fmaf(in96[k], up2_w0[k*64 + t], a);
        h[t] = silu_f(a);
    }
    __syncthreads();
    {
        float a = up2_b1[t] + e1v;
        #pragma unroll 8
        for (int k = 0; k < 64; k++) a = fmaf(h[k], up2_w1[k*64 + t], a);
        agg[96 + t] = a;
    }
    __syncthreads();
    if (t < 3) {
        float a = no_b0[t];
        for (int k = 0; k < 160; k++) a = fmaf(agg[k], no_w0[k*3 + t], a);
        t3[t] = silu_f(a);
    }
    for (int i = t; i < 160; i += 64) atomicAdd(&g_aggsum[i], agg[i]);
    __syncthreads();
    if (t < 3) {
        int c = charges[n];
        float o = no_embed[c*3 + t];
        #pragma unroll
        for (int k = 0; k < 3; k++) o = fmaf(t3[k], no_w1[k*3 + t], o);
        out[n*3 + t] = o;
    }

    __threadfence();
    if (t == 0) lastFlag = (atomicAdd(&g_done, 1u) == (unsigned)(NN - 1)) ? 1u : 0u;
    __syncthreads();
    if (lastFlag) {
        __shared__ float red[64];
        float p = 0.0f;
        for (int i = t; i < 160; i += 64) p += g_aggsum[i] * go_w0[i];
        red[t] = p;
        __syncthreads();
        for (int sft = 32; sft > 0; sft >>= 1) {
            if (t < sft) red[t] += red[t + sft];
            __syncthreads();
        }
        if (t == 0) {
            float hh = silu_f(red[0] * (1.0f / (float)NN) + go_b0[0]);
            out[NN*3] = fmaf(hh, go_w1[0], go_b1[0]);
        }
    }
}

extern "C" void kernel_launch(void* const* d_in, const int* in_sizes, int n_in,
                              void* d_out, int out_size)
{
    const float* nuclei      = (const float*)d_in[0];
    const int*   charges     = (const int*)  d_in[1];
    const float* embed_table = (const float*)d_in[3];
    const float* mp1_w0 = (const float*)d_in[4];
    const float* mp1_b0 = (const float*)d_in[5];
    const float* mp1_w1 = (const float*)d_in[6];
    const float* mp1_b1 = (const float*)d_in[7];
    const float* up1_w0 = (const float*)d_in[8];
    const float* up1_b0 = (const float*)d_in[9];
    const float* up1_w1 = (const float*)d_in[10];
    const float* up1_b1 = (const float*)d_in[11];
    const float* mp2_w0 = (const float*)d_in[12];
    const float* mp2_b0 = (const float*)d_in[13];
    const float* mp2_w1 = (const float*)d_in[14];
    const float* mp2_b1 = (const float*)d_in[15];
    const float* up2_w0 = (const float*)d_in[16];
    const float* up2_b0 = (const float*)d_in[17];
    const float* up2_w1 = (const float*)d_in[18];
    const float* up2_b1 = (const float*)d_in[19];
    const float* no_w0  = (const float*)d_in[20];
    const float* no_b0  = (const float*)d_in[21];
    const float* no_w1  = (const float*)d_in[22];
    const float* no_emb = (const float*)d_in[23];
    const float* go_w0  = (const float*)d_in[24];
    const float* go_b0  = (const float*)d_in[25];
    const float* go_w1  = (const float*)d_in[26];
    const float* go_b1  = (const float*)d_in[27];
    float* out = (float*)d_out;

    void* cwAddr = nullptr;
    cudaGetSymbolAddress(&cwAddr, cWe);
    cudaMemcpyAsync((char*)cwAddr,        mp1_w0 + 64*32,  4096, cudaMemcpyDeviceToDevice);
    cudaMemcpyAsync((char*)cwAddr + 4096, mp2_w0 + 128*32, 4096, cudaMemcpyDeviceToDevice);

    prep_kernel<<<NN*32/256, 256>>>(embed_table, charges, mp1_w0, mp1_b0);
    edge_kernel<0><<<EDGE_GRID, 256>>>(nuclei);
    node1_kernel<<<NN, 64>>>(mp1_w1, mp1_b1, up1_w0, up1_b0, up1_w1, up1_b1, mp2_w0, mp2_b0);
    edge_kernel<1><<<EDGE_GRID, 256>>>(nuclei);
    node2_kernel<<<NN, 64>>>(charges, mp2_w1, mp2_b1, up2_w0, up2_b0, up2_w1, up2_b1,
                             no_w0, no_b0, no_w1, no_emb,
                             go_w0, go_b0, go_w1, go_b1, out);
}